// round 2
// baseline (speedup 1.0000x reference)
#include <cuda_runtime.h>
#include <math.h>

// Problem constants
#define SEQ     1024      // inner batch (M of the recurrent GEMMs)
#define INPUT_D 512
#define HID     1024
#define GATES_N 4096      // 4*HID
#define STEPS   128
#define OUT_D   1000

// Scratch (device globals; no cudaMalloc allowed)
__device__ float g_h[SEQ * HID];
__device__ float g_c[SEQ * HID];
__device__ float g_gates[SEQ * GATES_N];
__device__ float g_hlast[STEPS * HID];

// ---------------------------------------------------------------------------
// Fused dual-K GEMM: out[m][n] = xscale * sum_k X[m][k]*Wx[n][k]
//                              +          sum_k H[m][k]*Wh[n][k]
//                              + b1[n] + b2[n]
// M=1024, N=4096 fixed. Classic 128x128 tile, BK=8, 256 threads, 8x8 microtile.
// ---------------------------------------------------------------------------
__global__ __launch_bounds__(256)
void gemm_gates_kernel(const float* __restrict__ X,
                       const float* __restrict__ Hm,
                       const float* __restrict__ Wx,
                       const float* __restrict__ Wh,
                       const float* __restrict__ b1,
                       const float* __restrict__ b2,
                       float* __restrict__ out,
                       int Kx, int Kh, float xscale)
{
    __shared__ float As[8][128];
    __shared__ float Bs[8][128];

    const int bm = blockIdx.y * 128;
    const int bn = blockIdx.x * 128;
    const int tid = threadIdx.x;
    const int tx = tid & 15;        // 0..15 -> N microtile
    const int ty = tid >> 4;        // 0..15 -> M microtile

    // loader mapping: 256 threads, each loads one float4 per tile
    const int lr = tid >> 1;        // 0..127 row within tile
    const int lc = (tid & 1) * 4;   // 0 or 4

    float acc[8][8];
#pragma unroll
    for (int i = 0; i < 8; i++)
#pragma unroll
        for (int j = 0; j < 8; j++) acc[i][j] = 0.0f;

#pragma unroll 1
    for (int pass = 0; pass < 2; ++pass) {
        const float* A = pass ? Hm : X;
        const float* W = pass ? Wh : Wx;
        const int    K = pass ? Kh : Kx;
        const float  s = pass ? 1.0f : xscale;

#pragma unroll 1
        for (int k0 = 0; k0 < K; k0 += 8) {
            const float4 av = *reinterpret_cast<const float4*>(A + (size_t)(bm + lr) * K + k0 + lc);
            const float4 bv = *reinterpret_cast<const float4*>(W + (size_t)(bn + lr) * K + k0 + lc);
            __syncthreads();   // protect smem from previous iteration's readers
            As[lc + 0][lr] = av.x * s;
            As[lc + 1][lr] = av.y * s;
            As[lc + 2][lr] = av.z * s;
            As[lc + 3][lr] = av.w * s;
            Bs[lc + 0][lr] = bv.x;
            Bs[lc + 1][lr] = bv.y;
            Bs[lc + 2][lr] = bv.z;
            Bs[lc + 3][lr] = bv.w;
            __syncthreads();

#pragma unroll
            for (int kk = 0; kk < 8; kk++) {
                float a[8], b[8];
#pragma unroll
                for (int i = 0; i < 8; i++) a[i] = As[kk][ty * 8 + i];
#pragma unroll
                for (int j = 0; j < 8; j++) b[j] = Bs[kk][tx * 8 + j];
#pragma unroll
                for (int i = 0; i < 8; i++)
#pragma unroll
                    for (int j = 0; j < 8; j++)
                        acc[i][j] += a[i] * b[j];
            }
        }
    }

    // epilogue: add biases, write gates
#pragma unroll
    for (int i = 0; i < 8; i++) {
        const int row = bm + ty * 8 + i;
        float* orow = out + (size_t)row * GATES_N + bn;
#pragma unroll
        for (int j = 0; j < 8; j++) {
            const int col = bn + tx * 8 + j;
            orow[tx * 8 + j] = acc[i][j] + b1[col] + b2[col];
        }
    }
}

// ---------------------------------------------------------------------------
// Pointwise LSTM cell update (torch gate order i, f, g, o).
// In-place update of h, c. Optionally captures row 1023 of new h.
// ---------------------------------------------------------------------------
__global__ __launch_bounds__(256)
void lstm_cell_kernel(const float* __restrict__ gates,
                      float* __restrict__ h,
                      float* __restrict__ c,
                      float* __restrict__ hlast)
{
    const int idx = blockIdx.x * blockDim.x + threadIdx.x;   // 0 .. SEQ*HID-1
    const int m = idx >> 10;          // row (HID == 1024)
    const int j = idx & 1023;

    const float* gr = gates + (size_t)m * GATES_N;
    const float gi = gr[j];
    const float gf = gr[j + HID];
    const float gg = gr[j + 2 * HID];
    const float go = gr[j + 3 * HID];

    const float si = 1.0f / (1.0f + expf(-gi));
    const float sf = 1.0f / (1.0f + expf(-gf));
    const float so = 1.0f / (1.0f + expf(-go));
    const float tg = tanhf(gg);

    const float cn = sf * c[idx] + si * tg;
    const float hn = so * tanhf(cn);

    c[idx] = cn;
    h[idx] = hn;
    if (hlast != nullptr && m == SEQ - 1) hlast[j] = hn;
}

// ---------------------------------------------------------------------------
// Zero-init h, c (graph replays must be deterministic)
// ---------------------------------------------------------------------------
__global__ void zero_hc_kernel()
{
    const int idx = blockIdx.x * blockDim.x + threadIdx.x;
    if (idx < SEQ * HID) { g_h[idx] = 0.0f; g_c[idx] = 0.0f; }
}

// ---------------------------------------------------------------------------
// Final FC: out[t][n] = sum_k Hlast[t][k] * Wfc[n][k] + bfc[n]
// One block per t (128 blocks), hrow cached in smem.
// ---------------------------------------------------------------------------
__global__ __launch_bounds__(256)
void fc_kernel(const float* __restrict__ Hl,
               const float* __restrict__ Wfc,
               const float* __restrict__ bfc,
               float* __restrict__ out)
{
    __shared__ float hrow[HID];
    const int t = blockIdx.x;
    for (int k = threadIdx.x; k < HID; k += 256) hrow[k] = Hl[(size_t)t * HID + k];
    __syncthreads();

    for (int n = threadIdx.x; n < OUT_D; n += 256) {
        const float* w = Wfc + (size_t)n * HID;
        float s = 0.0f;
#pragma unroll 8
        for (int k = 0; k < HID; k++) s = fmaf(hrow[k], w[k], s);
        out[(size_t)t * OUT_D + n] = s + bfc[n];
    }
}

// ---------------------------------------------------------------------------
extern "C" void kernel_launch(void* const* d_in, const int* in_sizes, int n_in,
                              void* d_out, int out_size)
{
    const float* x     = (const float*)d_in[0];   // [128,1024,512]
    const float* w_ih1 = (const float*)d_in[1];   // [4096,512]
    const float* w_hh1 = (const float*)d_in[2];   // [4096,1024]
    const float* b_ih1 = (const float*)d_in[3];   // [4096]
    const float* b_hh1 = (const float*)d_in[4];
    const float* w_ih2 = (const float*)d_in[5];   // [4096,512]
    const float* w_hh2 = (const float*)d_in[6];   // [4096,1024]
    const float* b_ih2 = (const float*)d_in[7];
    const float* b_hh2 = (const float*)d_in[8];
    const float* w_fc  = (const float*)d_in[9];   // [1000,1024]
    const float* b_fc  = (const float*)d_in[10];  // [1000]
    float* out = (float*)d_out;                   // [128,1000]

    float *h, *c, *gates, *hlast;
    cudaGetSymbolAddress((void**)&h,     g_h);
    cudaGetSymbolAddress((void**)&c,     g_c);
    cudaGetSymbolAddress((void**)&gates, g_gates);
    cudaGetSymbolAddress((void**)&hlast, g_hlast);

    // zero carry
    zero_hc_kernel<<<(SEQ * HID + 255) / 256, 256>>>();

    const dim3 gemm_grid(GATES_N / 128, SEQ / 128);   // (32, 8)
    const dim3 gemm_block(256);
    const int  cell_blocks = (SEQ * HID) / 256;

    for (int t = 0; t < STEPS; ++t) {
        const float* xt = x + (size_t)t * SEQ * INPUT_D;

        // layer 1: gates = 255*xt@Wih1^T + h@Whh1^T + b
        gemm_gates_kernel<<<gemm_grid, gemm_block>>>(
            xt, h, w_ih1, w_hh1, b_ih1, b_hh1, gates, INPUT_D, HID, 255.0f);
        lstm_cell_kernel<<<cell_blocks, 256>>>(gates, h, c, nullptr);

        // layer 2: gates = 255*xt@Wih2^T + h@Whh2^T + b   (input is xt again)
        gemm_gates_kernel<<<gemm_grid, gemm_block>>>(
            xt, h, w_ih2, w_hh2, b_ih2, b_hh2, gates, INPUT_D, HID, 255.0f);
        lstm_cell_kernel<<<cell_blocks, 256>>>(gates, h, c, hlast + (size_t)t * HID);
    }

    fc_kernel<<<STEPS, 256>>>(hlast, w_fc, b_fc, out);
}

// round 4
// speedup vs baseline: 3.0862x; 3.0862x over previous
#include <cuda_runtime.h>
#include <cuda_bf16.h>
#include <cstdint>
#include <math.h>

#define SEQ     1024
#define INPUT_D 512
#define HID     1024
#define GATES_N 4096
#define STEPS   128
#define OUT_D   1000

// ---------------- device scratch (no cudaMalloc allowed) ----------------
__device__ __nv_bfloat16 g_xhi[(size_t)STEPS * SEQ * INPUT_D];
__device__ __nv_bfloat16 g_xlo[(size_t)STEPS * SEQ * INPUT_D];
__device__ __nv_bfloat16 g_wxh[2][GATES_N * INPUT_D];
__device__ __nv_bfloat16 g_wxl[2][GATES_N * INPUT_D];
__device__ __nv_bfloat16 g_whh[2][GATES_N * HID];
__device__ __nv_bfloat16 g_whl[2][GATES_N * HID];
__device__ __nv_bfloat16 g_hhi[SEQ * HID];
__device__ __nv_bfloat16 g_hlo[SEQ * HID];
__device__ float g_c[SEQ * HID];
__device__ float g_gates[(size_t)SEQ * GATES_N];
__device__ float g_hlast[STEPS * HID];

// ---------------- helpers ----------------
__device__ __forceinline__ uint32_t smem_u32(const void* p) {
    return (uint32_t)__cvta_generic_to_shared(p);
}
__device__ __forceinline__ void cp16(uint32_t saddr, const void* gaddr) {
    asm volatile("cp.async.cg.shared.global [%0], [%1], 16;" :: "r"(saddr), "l"(gaddr) : "memory");
}
#define CP_COMMIT() asm volatile("cp.async.commit_group;" ::: "memory")
#define CP_WAIT(n)  asm volatile("cp.async.wait_group %0;" :: "n"(n) : "memory")

__device__ __forceinline__ uint32_t sw128(uint32_t off) {
    return off ^ ((off >> 3) & 0x70);
}

// ---------------- GEMM (mma.sync bf16, 3x-bf16 fp32 emulation) ----------------
// out[m][n] = sum over 72 chunks of K=64:  A_chunk[m][k] * B_chunk[n][k]  + b1[n] + b2[n]
// chunks = 3 products x (x-part K=512 + h-part K=1024)
#define TILE_M   128
#define TILE_N   128
#define CHUNK_K  64
#define NS       3
#define NCHUNKS  72
#define A_BYTES  (TILE_M * CHUNK_K * 2)      // 16 KB
#define STAGE_BYTES (2 * A_BYTES)            // 32 KB (A + B)
#define SMEM_DYN (NS * STAGE_BYTES)          // 96 KB

__global__ __launch_bounds__(256, 2)
void gemm_tc(const __nv_bfloat16* __restrict__ xhi, const __nv_bfloat16* __restrict__ xlo,
             const __nv_bfloat16* __restrict__ hhi, const __nv_bfloat16* __restrict__ hlo,
             const __nv_bfloat16* __restrict__ wxh, const __nv_bfloat16* __restrict__ wxl,
             const __nv_bfloat16* __restrict__ whh, const __nv_bfloat16* __restrict__ whl,
             const float* __restrict__ b1, const float* __restrict__ b2,
             float* __restrict__ out)
{
    extern __shared__ __align__(1024) char smem_raw[];
    const uint32_t sbase = smem_u32(smem_raw);

    const int tid = threadIdx.x;
    const int wid = tid >> 5;
    const int lane = tid & 31;
    const int wm = wid & 1;          // 2 warps along M (64 rows each)
    const int wn = wid >> 1;         // 4 warps along N (32 cols each)
    const int bn = blockIdx.x * TILE_N;
    const int bm = blockIdx.y * TILE_M;

    // chunk -> (A source, B source, k0, k stride)
    auto get_src = [&](int c, const __nv_bfloat16*& a, const __nv_bfloat16*& b,
                       int& k0, int& kst) {
        const int prod = c / 24;       // 0: hi*hi, 1: hi*lo, 2: lo*hi
        const int r = c - prod * 24;
        if (r < 8) {                   // x-part, K=512
            kst = INPUT_D; k0 = r * CHUNK_K;
            a = (prod == 2) ? xlo : xhi;
            b = (prod == 1) ? wxl : wxh;
        } else {                       // h-part, K=1024
            kst = HID; k0 = (r - 8) * CHUNK_K;
            a = (prod == 2) ? hlo : hhi;
            b = (prod == 1) ? whl : whh;
        }
    };

    // 16B-vector loader: A tile 128x64, B tile 128x64, 256 threads x (4+4) cp.async
    const int lrow = tid >> 3;            // 0..31 base row step
    const int lcol = (tid & 7) * 16;      // 16B block within 128B row
    auto load_chunk = [&](int c, int stage) {
        const __nv_bfloat16 *a, *b; int k0, kst;
        get_src(c, a, b, k0, kst);
        const uint32_t abase = sbase + stage * STAGE_BYTES;
        const uint32_t bbase = abase + A_BYTES;
#pragma unroll
        for (int v = 0; v < 4; v++) {
            const int row = v * 32 + lrow;
            cp16(abase + sw128(row * 128 + lcol),
                 a + (size_t)(bm + row) * kst + k0 + lcol / 2);
            cp16(bbase + sw128(row * 128 + lcol),
                 b + (size_t)(bn + row) * kst + k0 + lcol / 2);
        }
    };

    float acc[4][4][4];
#pragma unroll
    for (int i = 0; i < 4; i++)
#pragma unroll
        for (int j = 0; j < 4; j++)
#pragma unroll
            for (int q = 0; q < 4; q++) acc[i][j][q] = 0.0f;

    auto compute_chunk = [&](int stage) {
        const uint32_t abase = sbase + stage * STAGE_BYTES;
        const uint32_t bbase = abase + A_BYTES;
#pragma unroll
        for (int ks = 0; ks < 4; ks++) {
            // B fragments: 4 n-tiles of 8 cols; [n][k] row-major => non-trans ldmatrix
            uint32_t bf[4][2];
#pragma unroll
            for (int ntp = 0; ntp < 2; ntp++) {
                const int g = lane >> 3, l7 = lane & 7;
                const int nrow = wn * 32 + ntp * 16 + (g >> 1) * 8 + l7;
                const uint32_t addr = bbase + sw128(nrow * 128 + ks * 32 + (g & 1) * 16);
                asm volatile("ldmatrix.sync.aligned.m8n8.x4.shared.b16 {%0,%1,%2,%3}, [%4];"
                    : "=r"(bf[ntp * 2][0]), "=r"(bf[ntp * 2][1]),
                      "=r"(bf[ntp * 2 + 1][0]), "=r"(bf[ntp * 2 + 1][1])
                    : "r"(addr));
            }
#pragma unroll
            for (int mt = 0; mt < 4; mt++) {
                const int mrow = wm * 64 + mt * 16 + (lane & 15);
                const uint32_t aaddr = abase + sw128(mrow * 128 + ks * 32 + (lane >> 4) * 16);
                uint32_t a0, a1, a2, a3;
                asm volatile("ldmatrix.sync.aligned.m8n8.x4.shared.b16 {%0,%1,%2,%3}, [%4];"
                    : "=r"(a0), "=r"(a1), "=r"(a2), "=r"(a3) : "r"(aaddr));
#pragma unroll
                for (int nt = 0; nt < 4; nt++) {
                    asm volatile(
                        "mma.sync.aligned.m16n8k16.row.col.f32.bf16.bf16.f32 "
                        "{%0,%1,%2,%3}, {%4,%5,%6,%7}, {%8,%9}, {%0,%1,%2,%3};"
                        : "+f"(acc[mt][nt][0]), "+f"(acc[mt][nt][1]),
                          "+f"(acc[mt][nt][2]), "+f"(acc[mt][nt][3])
                        : "r"(a0), "r"(a1), "r"(a2), "r"(a3),
                          "r"(bf[nt][0]), "r"(bf[nt][1]));
                }
            }
        }
    };

    // prologue: stages 0..NS-2
#pragma unroll
    for (int p = 0; p < NS - 1; p++) { load_chunk(p, p); CP_COMMIT(); }

#pragma unroll 1
    for (int i = 0; i < NCHUNKS; i++) {
        CP_WAIT(NS - 2);          // chunk i resident (all but last pending group done)
        __syncthreads();          // all warps past compute(i-1): stage (i+NS-1)%NS free
        if (i + NS - 1 < NCHUNKS) load_chunk(i + NS - 1, (i + NS - 1) % NS);
        CP_COMMIT();              // one group per iter keeps the count uniform
        compute_chunk(i % NS);
    }

    // epilogue: c-frag m16n8: rows lane/4, lane/4+8; cols (lane%4)*2, +1
#pragma unroll
    for (int mt = 0; mt < 4; mt++) {
        const int m0 = bm + wm * 64 + mt * 16 + (lane >> 2);
#pragma unroll
        for (int nt = 0; nt < 4; nt++) {
            const int n0 = bn + wn * 32 + nt * 8 + (lane & 3) * 2;
            const float bs0 = b1[n0] + b2[n0];
            const float bs1 = b1[n0 + 1] + b2[n0 + 1];
            float2 v0, v1;
            v0.x = acc[mt][nt][0] + bs0; v0.y = acc[mt][nt][1] + bs1;
            v1.x = acc[mt][nt][2] + bs0; v1.y = acc[mt][nt][3] + bs1;
            *reinterpret_cast<float2*>(out + (size_t)m0 * GATES_N + n0) = v0;
            *reinterpret_cast<float2*>(out + (size_t)(m0 + 8) * GATES_N + n0) = v1;
        }
    }
}

// ---------------- pointwise kernels ----------------
__global__ void split_kernel(const float* __restrict__ src, __nv_bfloat16* __restrict__ hi,
                             __nv_bfloat16* __restrict__ lo, size_t n, float scale)
{
    const size_t i = (size_t)blockIdx.x * blockDim.x + threadIdx.x;
    if (i < n) {
        const float v = src[i] * scale;
        const __nv_bfloat16 h = __float2bfloat16(v);
        hi[i] = h;
        lo[i] = __float2bfloat16(v - __bfloat162float(h));
    }
}

__global__ void zero_state_kernel()
{
    const int i = blockIdx.x * blockDim.x + threadIdx.x;
    if (i < SEQ * HID) {
        g_hhi[i] = __float2bfloat16(0.f);
        g_hlo[i] = __float2bfloat16(0.f);
        g_c[i] = 0.f;
    }
}

__global__ __launch_bounds__(256)
void lstm_cell_kernel(const float* __restrict__ gates,
                      __nv_bfloat16* __restrict__ hhi, __nv_bfloat16* __restrict__ hlo,
                      float* __restrict__ c, float* __restrict__ hlast)
{
    const int idx = blockIdx.x * blockDim.x + threadIdx.x;
    const int m = idx >> 10;
    const int j = idx & 1023;
    const float* gr = gates + (size_t)m * GATES_N;
    const float gi = gr[j];
    const float gf = gr[j + HID];
    const float gg = gr[j + 2 * HID];
    const float go = gr[j + 3 * HID];

    const float si = 1.0f / (1.0f + expf(-gi));
    const float sf = 1.0f / (1.0f + expf(-gf));
    const float so = 1.0f / (1.0f + expf(-go));
    const float tg = tanhf(gg);

    const float cn = sf * c[idx] + si * tg;
    const float hn = so * tanhf(cn);
    c[idx] = cn;

    const __nv_bfloat16 hh = __float2bfloat16(hn);
    hhi[idx] = hh;
    hlo[idx] = __float2bfloat16(hn - __bfloat162float(hh));
    if (hlast != nullptr && m == SEQ - 1) hlast[j] = hn;
}

__global__ __launch_bounds__(256)
void fc_kernel(const float* __restrict__ Hl, const float* __restrict__ Wfc,
               const float* __restrict__ bfc, float* __restrict__ out)
{
    __shared__ float hrow[HID];
    const int t = blockIdx.x;
    for (int k = threadIdx.x; k < HID; k += 256) hrow[k] = Hl[(size_t)t * HID + k];
    __syncthreads();
    for (int n = threadIdx.x; n < OUT_D; n += 256) {
        const float* w = Wfc + (size_t)n * HID;
        float s = 0.f;
#pragma unroll 8
        for (int k = 0; k < HID; k++) s = fmaf(hrow[k], w[k], s);
        out[(size_t)t * OUT_D + n] = s + bfc[n];
    }
}

// ---------------- launch ----------------
extern "C" void kernel_launch(void* const* d_in, const int* in_sizes, int n_in,
                              void* d_out, int out_size)
{
    const float* x     = (const float*)d_in[0];
    const float* w_ih1 = (const float*)d_in[1];
    const float* w_hh1 = (const float*)d_in[2];
    const float* b_ih1 = (const float*)d_in[3];
    const float* b_hh1 = (const float*)d_in[4];
    const float* w_ih2 = (const float*)d_in[5];
    const float* w_hh2 = (const float*)d_in[6];
    const float* b_ih2 = (const float*)d_in[7];
    const float* b_hh2 = (const float*)d_in[8];
    const float* w_fc  = (const float*)d_in[9];
    const float* b_fc  = (const float*)d_in[10];
    float* out = (float*)d_out;

    __nv_bfloat16 *xhi, *xlo, *wxh, *wxl, *whh, *whl, *hhi, *hlo;
    float *c, *gates, *hlast;
    cudaGetSymbolAddress((void**)&xhi, g_xhi);
    cudaGetSymbolAddress((void**)&xlo, g_xlo);
    cudaGetSymbolAddress((void**)&wxh, g_wxh);
    cudaGetSymbolAddress((void**)&wxl, g_wxl);
    cudaGetSymbolAddress((void**)&whh, g_whh);
    cudaGetSymbolAddress((void**)&whl, g_whl);
    cudaGetSymbolAddress((void**)&hhi, g_hhi);
    cudaGetSymbolAddress((void**)&hlo, g_hlo);
    cudaGetSymbolAddress((void**)&c,     g_c);
    cudaGetSymbolAddress((void**)&gates, g_gates);
    cudaGetSymbolAddress((void**)&hlast, g_hlast);

    cudaFuncSetAttribute(gemm_tc, cudaFuncAttributeMaxDynamicSharedMemorySize, SMEM_DYN);

    // split inputs/weights into bf16 hi/lo (x folded with *255)
    {
        const size_t nx = (size_t)STEPS * SEQ * INPUT_D;
        split_kernel<<<(unsigned)((nx + 255) / 256), 256>>>(x, xhi, xlo, nx, 255.0f);
        const size_t nwx = (size_t)GATES_N * INPUT_D;
        const size_t nwh = (size_t)GATES_N * HID;
        split_kernel<<<(unsigned)((nwx + 255) / 256), 256>>>(w_ih1, wxh, wxl, nwx, 1.0f);
        split_kernel<<<(unsigned)((nwh + 255) / 256), 256>>>(w_hh1, whh, whl, nwh, 1.0f);
        split_kernel<<<(unsigned)((nwx + 255) / 256), 256>>>(w_ih2, wxh + nwx, wxl + nwx, nwx, 1.0f);
        split_kernel<<<(unsigned)((nwh + 255) / 256), 256>>>(w_hh2, whh + nwh, whl + nwh, nwh, 1.0f);
    }
    zero_state_kernel<<<(SEQ * HID + 255) / 256, 256>>>();

    const dim3 ggrid(GATES_N / TILE_N, SEQ / TILE_M);   // (32, 8)
    const int cell_blocks = (SEQ * HID) / 256;
    const size_t nwx = (size_t)GATES_N * INPUT_D;
    const size_t nwh = (size_t)GATES_N * HID;

    for (int t = 0; t < STEPS; ++t) {
        const __nv_bfloat16* xth = xhi + (size_t)t * SEQ * INPUT_D;
        const __nv_bfloat16* xtl = xlo + (size_t)t * SEQ * INPUT_D;

        gemm_tc<<<ggrid, 256, SMEM_DYN>>>(xth, xtl, hhi, hlo,
                                          wxh, wxl, whh, whl,
                                          b_ih1, b_hh1, gates);
        lstm_cell_kernel<<<cell_blocks, 256>>>(gates, hhi, hlo, c, nullptr);

        gemm_tc<<<ggrid, 256, SMEM_DYN>>>(xth, xtl, hhi, hlo,
                                          wxh + nwx, wxl + nwx, whh + nwh, whl + nwh,
                                          b_ih2, b_hh2, gates);
        lstm_cell_kernel<<<cell_blocks, 256>>>(gates, hhi, hlo, c, hlast + (size_t)t * HID);
    }

    fc_kernel<<<STEPS, 256>>>(hlast, w_fc, b_fc, out);
}